// round 1
// baseline (speedup 1.0000x reference)
#include <cuda_runtime.h>
#include <cuda_bf16.h>
#include <math.h>

#define NN 100000
#define EE 1000000
#define RR 500
#define DD 64
#define NB_N 98            // ceil(100000/1024)
#define SPLIT 8

// ---------------- scratch (device globals; no runtime allocation) -------------
__device__ float g_P1[NN * DD];
__device__ float g_P2[NN * DD];
__device__ float g_q1[NN];
__device__ float g_q2[NN];
__device__ float g_P3p[RR * DD];
__device__ float g_q3[RR];
__device__ float g_R2[RR * DD];
__device__ float g_M1[DD * DD];
__device__ float g_M2[DD * DD];
__device__ float g_M3[DD * DD];
__device__ float g_c0[DD];
__device__ float g_bexp[EE];
__device__ int   g_src_cnt[NN];
__device__ int   g_rel_cnt[RR];
__device__ int   g_src_off[NN + 1];
__device__ int   g_rel_off[RR + 1];
__device__ int   g_src_cur[NN];
__device__ int   g_rel_cur[RR];
__device__ int   g_src_edges[EE];
__device__ int   g_rel_edges[EE];
__device__ int   g_blocksum[128];
__device__ float g_relsum[RR * 128];

// ---------------- helpers ----------------------------------------------------
__device__ __forceinline__ int blockExScan(int v, int* warpSums) {
    int lane = threadIdx.x & 31;
    int wid  = threadIdx.x >> 5;
    int nw   = blockDim.x >> 5;
    int inc = v;
#pragma unroll
    for (int o = 1; o < 32; o <<= 1) {
        int t = __shfl_up_sync(0xffffffffu, inc, o);
        if (lane >= o) inc += t;
    }
    if (lane == 31) warpSums[wid] = inc;
    __syncthreads();
    if (wid == 0) {
        int w = (lane < nw) ? warpSums[lane] : 0;
#pragma unroll
        for (int o = 1; o < 32; o <<= 1) {
            int t = __shfl_up_sync(0xffffffffu, w, o);
            if (lane >= o) w += t;
        }
        if (lane < nw) warpSums[lane] = w;
    }
    __syncthreads();
    int base = (wid > 0) ? warpSums[wid - 1] : 0;
    return base + inc - v;   // exclusive
}

// ---------------- 1. composed weight matrices --------------------------------
// M1 = W_fc[:,0:64]   @ W_ent
// M2 = W_fc[:,64:128] @ W_ent
// M3 = W_fc[:,128:192]@ W_relL
// c0 = b_fc + W_fcA@b_ent + W_fcB@b_ent + W_fcC@b_relL
__global__ void k_precompute(const float* __restrict__ W_ent,
                             const float* __restrict__ W_relL,
                             const float* __restrict__ W_fc,
                             const float* __restrict__ b_ent,
                             const float* __restrict__ b_relL,
                             const float* __restrict__ b_fc) {
    int tid = threadIdx.x;
    for (int idx = tid; idx < DD * DD; idx += blockDim.x) {
        int i = idx >> 6, j = idx & 63;
        float a1 = 0.f, a2 = 0.f, a3 = 0.f;
#pragma unroll 8
        for (int k = 0; k < DD; k++) {
            float e = W_ent[k * DD + j];
            a1 = fmaf(W_fc[i * 192 + k], e, a1);
            a2 = fmaf(W_fc[i * 192 + 64 + k], e, a2);
            a3 = fmaf(W_fc[i * 192 + 128 + k], W_relL[k * DD + j], a3);
        }
        g_M1[idx] = a1; g_M2[idx] = a2; g_M3[idx] = a3;
    }
    if (tid < DD) {
        float c = b_fc[tid];
#pragma unroll 8
        for (int k = 0; k < DD; k++) {
            c = fmaf(W_fc[tid * 192 + k], b_ent[k], c);
            c = fmaf(W_fc[tid * 192 + 64 + k], b_ent[k], c);
            c = fmaf(W_fc[tid * 192 + 128 + k], b_relL[k], c);
        }
        g_c0[tid] = c;
    }
}

// ---------------- 2. relation tables: P3p, q3, R2 ----------------------------
__global__ void k_rel_proj(const float* __restrict__ rel_embed,
                           const float* __restrict__ W_relL,
                           const float* __restrict__ b_relL,
                           const float* __restrict__ W_rel2,
                           const float* __restrict__ b_rel2,
                           const float* __restrict__ W_a,
                           const float* __restrict__ b_a) {
    int r = blockIdx.x * 4 + (threadIdx.x >> 5);
    int lane = threadIdx.x & 31;
    if (r >= RR) return;
    float x0 = rel_embed[r * DD + lane];
    float x1 = rel_embed[r * DD + 32 + lane];
    int i0 = lane, i1 = lane + 32;
    float rl0 = b_relL[i0], rl1 = b_relL[i1];
    float p0 = g_c0[i0], p1 = g_c0[i1];
#pragma unroll
    for (int k = 0; k < DD; k++) {
        float xk = (k < 32) ? __shfl_sync(0xffffffffu, x0, k)
                            : __shfl_sync(0xffffffffu, x1, k - 32);
        rl0 = fmaf(xk, W_relL[i0 * DD + k], rl0);
        rl1 = fmaf(xk, W_relL[i1 * DD + k], rl1);
        p0  = fmaf(xk, g_M3[i0 * DD + k], p0);
        p1  = fmaf(xk, g_M3[i1 * DD + k], p1);
    }
    g_P3p[r * DD + i0] = p0;
    g_P3p[r * DD + i1] = p1;
    // R2 = relL @ W_rel2^T + b_rel2
    float r20 = b_rel2[i0], r21 = b_rel2[i1];
#pragma unroll
    for (int k = 0; k < DD; k++) {
        float rk = (k < 32) ? __shfl_sync(0xffffffffu, rl0, k)
                            : __shfl_sync(0xffffffffu, rl1, k - 32);
        r20 = fmaf(rk, W_rel2[i0 * DD + k], r20);
        r21 = fmaf(rk, W_rel2[i1 * DD + k], r21);
    }
    g_R2[r * DD + i0] = r20;
    g_R2[r * DD + i1] = r21;
    // q3 = dot(P3p, a) + b_a
    float q = fmaf(p0, W_a[i0], p1 * W_a[i1]);
#pragma unroll
    for (int o = 16; o > 0; o >>= 1) q += __shfl_xor_sync(0xffffffffu, q, o);
    if (lane == 0) g_q3[r] = q + b_a[0];
}

// ---------------- 3. node tables: P1, P2, q1, q2 -----------------------------
__global__ void __launch_bounds__(128) k_node_proj(const float* __restrict__ ent,
                                                   const float* __restrict__ W_a) {
    __shared__ float sM1[DD * DD];
    __shared__ float sM2[DD * DD];
    __shared__ float sA[DD];
    for (int idx = threadIdx.x; idx < DD * DD; idx += 128) {
        sM1[idx] = g_M1[idx];
        sM2[idx] = g_M2[idx];
    }
    if (threadIdx.x < DD) sA[threadIdx.x] = W_a[threadIdx.x];
    __syncthreads();

    int node = blockIdx.x * 128 + threadIdx.x;
    if (node >= NN) return;

    float xs[DD];
    const float4* xr = (const float4*)(ent + node * DD);
#pragma unroll
    for (int u = 0; u < 16; u++) {
        float4 v = xr[u];
        xs[4 * u + 0] = v.x; xs[4 * u + 1] = v.y;
        xs[4 * u + 2] = v.z; xs[4 * u + 3] = v.w;
    }
    float q1a = 0.f;
#pragma unroll 1
    for (int i = 0; i < DD; i += 4) {
        float a0 = 0.f, a1 = 0.f, a2 = 0.f, a3 = 0.f;
#pragma unroll
        for (int k = 0; k < DD; k++) {
            float xk = xs[k];
            a0 = fmaf(xk, sM1[(i + 0) * DD + k], a0);
            a1 = fmaf(xk, sM1[(i + 1) * DD + k], a1);
            a2 = fmaf(xk, sM1[(i + 2) * DD + k], a2);
            a3 = fmaf(xk, sM1[(i + 3) * DD + k], a3);
        }
        float4 v = make_float4(a0, a1, a2, a3);
        *(float4*)&g_P1[node * DD + i] = v;
        q1a = fmaf(a0, sA[i], q1a); q1a = fmaf(a1, sA[i + 1], q1a);
        q1a = fmaf(a2, sA[i + 2], q1a); q1a = fmaf(a3, sA[i + 3], q1a);
    }
    g_q1[node] = q1a;

    float q2a = 0.f;
#pragma unroll 1
    for (int i = 0; i < DD; i += 4) {
        float a0 = 0.f, a1 = 0.f, a2 = 0.f, a3 = 0.f;
#pragma unroll
        for (int k = 0; k < DD; k++) {
            float xk = xs[k];
            a0 = fmaf(xk, sM2[(i + 0) * DD + k], a0);
            a1 = fmaf(xk, sM2[(i + 1) * DD + k], a1);
            a2 = fmaf(xk, sM2[(i + 2) * DD + k], a2);
            a3 = fmaf(xk, sM2[(i + 3) * DD + k], a3);
        }
        float4 v = make_float4(a0, a1, a2, a3);
        *(float4*)&g_P2[node * DD + i] = v;
        q2a = fmaf(a0, sA[i], q2a); q2a = fmaf(a1, sA[i + 1], q2a);
        q2a = fmaf(a2, sA[i + 2], q2a); q2a = fmaf(a3, sA[i + 3], q2a);
    }
    g_q2[node] = q2a;
}

// ---------------- 4. per-edge: exp(leaky(logit)) + bin counts ----------------
__global__ void k_edge_pre(const int* __restrict__ src,
                           const int* __restrict__ dst,
                           const int* __restrict__ rel) {
    int e = blockIdx.x * blockDim.x + threadIdx.x;
    if (e >= EE) return;
    int s = src[e], d = dst[e], r = rel[e];
    float lg = g_q1[s] + g_q2[d] + g_q3[r];
    lg = (lg >= 0.f) ? lg : 0.01f * lg;
    g_bexp[e] = expf(lg);
    atomicAdd(&g_src_cnt[s], 1);
    atomicAdd(&g_rel_cnt[r], 1);
}

// ---------------- 5. scans / CSR build ---------------------------------------
__global__ void k_scan1() {
    __shared__ int ws[32];
    int i = blockIdx.x * 1024 + threadIdx.x;
    int v = (i < NN) ? g_src_cnt[i] : 0;
    int lane = threadIdx.x & 31, wid = threadIdx.x >> 5;
#pragma unroll
    for (int o = 16; o > 0; o >>= 1) v += __shfl_down_sync(0xffffffffu, v, o);
    if (lane == 0) ws[wid] = v;
    __syncthreads();
    if (wid == 0) {
        int s = ws[lane];
#pragma unroll
        for (int o = 16; o > 0; o >>= 1) s += __shfl_down_sync(0xffffffffu, s, o);
        if (lane == 0) g_blocksum[blockIdx.x] = s;
    }
}
__global__ void k_scan2() {
    __shared__ int ws[32];
    int v = (threadIdx.x < NB_N) ? g_blocksum[threadIdx.x] : 0;
    int ex = blockExScan(v, ws);
    if (threadIdx.x < NB_N) g_blocksum[threadIdx.x] = ex;
    if (threadIdx.x == 0) g_src_off[NN] = EE;
}
__global__ void k_scan3() {
    __shared__ int ws[32];
    int i = blockIdx.x * 1024 + threadIdx.x;
    int v = (i < NN) ? g_src_cnt[i] : 0;
    int ex = blockExScan(v, ws) + g_blocksum[blockIdx.x];
    if (i < NN) { g_src_off[i] = ex; g_src_cur[i] = ex; }
}
__global__ void k_relscan() {
    __shared__ int ws[32];
    int i = threadIdx.x;
    int v = (i < RR) ? g_rel_cnt[i] : 0;
    int ex = blockExScan(v, ws);
    if (i < RR) { g_rel_off[i] = ex; g_rel_cur[i] = ex; }
    if (i == 0) g_rel_off[RR] = EE;
}
__global__ void k_fill(const int* __restrict__ src, const int* __restrict__ rel) {
    int e = blockIdx.x * blockDim.x + threadIdx.x;
    if (e >= EE) return;
    int s = src[e], r = rel[e];
    int p0 = atomicAdd(&g_src_cur[s], 1);
    g_src_edges[p0] = e;
    int p1 = atomicAdd(&g_rel_cur[r], 1);
    g_rel_edges[p1] = e;
}

// ---------------- 6. node aggregation: h_ent ---------------------------------
// warp per node; h = P1[n] + (sum_e b_e*(P2[dst]+P3p[rel])) / (sum_e b_e)
__global__ void __launch_bounds__(256) k_node_agg(const int* __restrict__ dst,
                                                  const int* __restrict__ rel,
                                                  float* __restrict__ out) {
    int wid = threadIdx.x >> 5;
    int lane = threadIdx.x & 31;
    int n = blockIdx.x * 8 + wid;
    if (n >= NN) return;
    int j = g_src_off[n];
    int j1 = g_src_off[n + 1];
    float acc0 = 0.f, acc1 = 0.f, bsum = 0.f;
    for (; j + 2 <= j1; j += 2) {
        int eA = g_src_edges[j], eB = g_src_edges[j + 1];
        int dA = dst[eA], rA = rel[eA];
        int dB = dst[eB], rB = rel[eB];
        float bA = g_bexp[eA], bB = g_bexp[eB];
        float vA0 = g_P2[dA * DD + lane] + g_P3p[rA * DD + lane];
        float vA1 = g_P2[dA * DD + 32 + lane] + g_P3p[rA * DD + 32 + lane];
        float vB0 = g_P2[dB * DD + lane] + g_P3p[rB * DD + lane];
        float vB1 = g_P2[dB * DD + 32 + lane] + g_P3p[rB * DD + 32 + lane];
        acc0 = fmaf(bA, vA0, acc0); acc1 = fmaf(bA, vA1, acc1);
        acc0 = fmaf(bB, vB0, acc0); acc1 = fmaf(bB, vB1, acc1);
        bsum += bA + bB;
    }
    if (j < j1) {
        int e = g_src_edges[j];
        int d = dst[e], r = rel[e];
        float b = g_bexp[e];
        acc0 = fmaf(b, g_P2[d * DD + lane] + g_P3p[r * DD + lane], acc0);
        acc1 = fmaf(b, g_P2[d * DD + 32 + lane] + g_P3p[r * DD + 32 + lane], acc1);
        bsum += b;
    }
    float h0, h1;
    if (j1 > g_src_off[n]) {
        float inv = 1.f / bsum;
        h0 = g_P1[n * DD + lane] + acc0 * inv;
        h1 = g_P1[n * DD + 32 + lane] + acc1 * inv;
    } else {
        h0 = 0.f; h1 = 0.f;
    }
    out[n * DD + lane] = h0;
    out[n * DD + 32 + lane] = h1;
}

// ---------------- 7. relation pooling sums -----------------------------------
// grid = RR*SPLIT CTAs of 128 threads; thread t: t<64 -> h_ent[src][t],
// t>=64 -> h_ent[dst][t-64]; register accumulation then 1 atomic per thread.
__global__ void __launch_bounds__(128) k_rel_pool(const int* __restrict__ src,
                                                  const int* __restrict__ dst,
                                                  const float* __restrict__ h) {
    int r = blockIdx.x >> 3;
    int part = blockIdx.x & (SPLIT - 1);
    int b0 = g_rel_off[r], b1 = g_rel_off[r + 1];
    int len = b1 - b0;
    int per = (len + SPLIT - 1) >> 3;
    int j0 = b0 + part * per;
    int j1 = min(j0 + per, b1);
    if (j0 >= j1) return;
    int t = threadIdx.x;
    bool isSrc = (t < 64);
    int dim = isSrc ? t : (t - 64);
    const int* nodeArr = isSrc ? src : dst;
    float acc = 0.f;
    int j = j0;
    for (; j + 4 <= j1; j += 4) {
        int e0 = g_rel_edges[j + 0], e1 = g_rel_edges[j + 1];
        int e2 = g_rel_edges[j + 2], e3 = g_rel_edges[j + 3];
        int n0 = nodeArr[e0], n1 = nodeArr[e1], n2 = nodeArr[e2], n3 = nodeArr[e3];
        float v0 = h[n0 * DD + dim];
        float v1 = h[n1 * DD + dim];
        float v2 = h[n2 * DD + dim];
        float v3 = h[n3 * DD + dim];
        acc += (v0 + v1) + (v2 + v3);
    }
    for (; j < j1; j++) {
        int e = g_rel_edges[j];
        acc += h[nodeArr[e] * DD + dim];
    }
    atomicAdd(&g_relsum[r * 128 + t], acc);
}

// ---------------- 8. h_rel = mean @ W_rel3^T + b_rel3 ------------------------
__global__ void k_rel_out(const float* __restrict__ W_rel3,
                          const float* __restrict__ b_rel3,
                          float* __restrict__ out) {
    int r = blockIdx.x * 4 + (threadIdx.x >> 5);
    int lane = threadIdx.x & 31;
    if (r >= RR) return;
    int cnt = g_rel_off[r + 1] - g_rel_off[r];
    float inv = 1.f / (float)max(cnt, 1);
    int i0 = lane, i1 = lane + 32;
    float h0 = b_rel3[i0], h1 = b_rel3[i1];
#pragma unroll 4
    for (int jj = 0; jj < 128; jj++) {
        float m = g_relsum[r * 128 + jj] * inv;
        h0 = fmaf(W_rel3[i0 * 192 + jj], m, h0);
        h1 = fmaf(W_rel3[i1 * 192 + jj], m, h1);
    }
#pragma unroll 4
    for (int jj = 0; jj < 64; jj++) {
        float m = g_R2[r * DD + jj];
        h0 = fmaf(W_rel3[i0 * 192 + 128 + jj], m, h0);
        h1 = fmaf(W_rel3[i1 * 192 + 128 + jj], m, h1);
    }
    out[NN * DD + r * DD + i0] = h0;
    out[NN * DD + r * DD + i1] = h1;
}

// ---------------- launcher ---------------------------------------------------
extern "C" void kernel_launch(void* const* d_in, const int* in_sizes, int n_in,
                              void* d_out, int out_size) {
    const float* ent_embed = (const float*)d_in[0];
    const float* rel_embed = (const float*)d_in[1];
    const float* W_ent  = (const float*)d_in[2];
    const float* b_ent  = (const float*)d_in[3];
    const float* W_relL = (const float*)d_in[4];
    const float* b_relL = (const float*)d_in[5];
    const float* W_rel2 = (const float*)d_in[6];
    const float* b_rel2 = (const float*)d_in[7];
    const float* W_rel3 = (const float*)d_in[8];
    const float* b_rel3 = (const float*)d_in[9];
    const float* W_a    = (const float*)d_in[10];
    const float* b_a    = (const float*)d_in[11];
    const float* W_fc   = (const float*)d_in[12];
    const float* b_fc   = (const float*)d_in[13];
    const int* src_idx = (const int*)d_in[14];
    const int* dst_idx = (const int*)d_in[15];
    const int* rel_idx = (const int*)d_in[16];
    float* out = (float*)d_out;

    void *pSrcCnt, *pRelCnt, *pRelSum;
    cudaGetSymbolAddress(&pSrcCnt, g_src_cnt);
    cudaGetSymbolAddress(&pRelCnt, g_rel_cnt);
    cudaGetSymbolAddress(&pRelSum, g_relsum);
    cudaMemsetAsync(pSrcCnt, 0, NN * sizeof(int), 0);
    cudaMemsetAsync(pRelCnt, 0, RR * sizeof(int), 0);
    cudaMemsetAsync(pRelSum, 0, RR * 128 * sizeof(float), 0);

    k_precompute<<<1, 256>>>(W_ent, W_relL, W_fc, b_ent, b_relL, b_fc);
    k_rel_proj<<<(RR + 3) / 4, 128>>>(rel_embed, W_relL, b_relL, W_rel2, b_rel2, W_a, b_a);
    k_node_proj<<<(NN + 127) / 128, 128>>>(ent_embed, W_a);
    k_edge_pre<<<(EE + 255) / 256, 256>>>(src_idx, dst_idx, rel_idx);
    k_scan1<<<NB_N, 1024>>>();
    k_scan2<<<1, 128>>>();
    k_scan3<<<NB_N, 1024>>>();
    k_relscan<<<1, 512>>>();
    k_fill<<<(EE + 255) / 256, 256>>>(src_idx, rel_idx);
    k_node_agg<<<(NN + 7) / 8, 256>>>(dst_idx, rel_idx, out);
    k_rel_pool<<<RR * SPLIT, 128>>>(src_idx, dst_idx, out);
    k_rel_out<<<(RR + 3) / 4, 128>>>(W_rel3, b_rel3, out);
}

// round 2
// speedup vs baseline: 1.6039x; 1.6039x over previous
#include <cuda_runtime.h>
#include <cuda_bf16.h>
#include <math.h>

#define NN 100000
#define EE 1000000
#define RR 500
#define DD 64
#define NB_N 98            // ceil(100000/1024)
#define SPLIT 8
#define RPAD 32            // 128B stride for relation counters (L2-slice spread)

// ---------------- scratch (device globals; no runtime allocation) -------------
__device__ float g_P1[NN * DD];
__device__ float g_P2[NN * DD];
__device__ float g_q1[NN];
__device__ float g_q2[NN];
__device__ float g_P3p[RR * DD];
__device__ float g_q3[RR];
__device__ float g_R2[RR * DD];
__device__ float g_M1[DD * DD];
__device__ float g_M2[DD * DD];
__device__ float g_M3[DD * DD];
__device__ float g_c0[DD];
__device__ float g_bexp[EE];
__device__ int   g_src_cnt[NN];
__device__ int   g_rel_cnt[RR * RPAD];
__device__ int   g_src_off[NN + 1];
__device__ int   g_rel_off[RR + 1];
__device__ int   g_src_cur[NN];
__device__ int   g_rel_cur[RR * RPAD];
__device__ int   g_src_edges[EE];
__device__ int   g_rel_edges[EE];
__device__ int   g_blocksum[128];
__device__ float g_relsum[RR * 128];

// ---------------- helpers ----------------------------------------------------
__device__ __forceinline__ int blockExScan(int v, int* warpSums) {
    int lane = threadIdx.x & 31;
    int wid  = threadIdx.x >> 5;
    int nw   = blockDim.x >> 5;
    int inc = v;
#pragma unroll
    for (int o = 1; o < 32; o <<= 1) {
        int t = __shfl_up_sync(0xffffffffu, inc, o);
        if (lane >= o) inc += t;
    }
    if (lane == 31) warpSums[wid] = inc;
    __syncthreads();
    if (wid == 0) {
        int w = (lane < nw) ? warpSums[lane] : 0;
#pragma unroll
        for (int o = 1; o < 32; o <<= 1) {
            int t = __shfl_up_sync(0xffffffffu, w, o);
            if (lane >= o) w += t;
        }
        if (lane < nw) warpSums[lane] = w;
    }
    __syncthreads();
    int base = (wid > 0) ? warpSums[wid - 1] : 0;
    return base + inc - v;   // exclusive
}

// ---------------- 1. composed weight matrices --------------------------------
__global__ void k_precompute(const float* __restrict__ W_ent,
                             const float* __restrict__ W_relL,
                             const float* __restrict__ W_fc,
                             const float* __restrict__ b_ent,
                             const float* __restrict__ b_relL,
                             const float* __restrict__ b_fc) {
    int tid = threadIdx.x;
    for (int idx = tid; idx < DD * DD; idx += blockDim.x) {
        int i = idx >> 6, j = idx & 63;
        float a1 = 0.f, a2 = 0.f, a3 = 0.f;
#pragma unroll 8
        for (int k = 0; k < DD; k++) {
            float e = W_ent[k * DD + j];
            a1 = fmaf(W_fc[i * 192 + k], e, a1);
            a2 = fmaf(W_fc[i * 192 + 64 + k], e, a2);
            a3 = fmaf(W_fc[i * 192 + 128 + k], W_relL[k * DD + j], a3);
        }
        g_M1[idx] = a1; g_M2[idx] = a2; g_M3[idx] = a3;
    }
    if (tid < DD) {
        float c = b_fc[tid];
#pragma unroll 8
        for (int k = 0; k < DD; k++) {
            c = fmaf(W_fc[tid * 192 + k], b_ent[k], c);
            c = fmaf(W_fc[tid * 192 + 64 + k], b_ent[k], c);
            c = fmaf(W_fc[tid * 192 + 128 + k], b_relL[k], c);
        }
        g_c0[tid] = c;
    }
}

// ---------------- 2. relation tables: P3p, q3, R2 ----------------------------
__global__ void k_rel_proj(const float* __restrict__ rel_embed,
                           const float* __restrict__ W_relL,
                           const float* __restrict__ b_relL,
                           const float* __restrict__ W_rel2,
                           const float* __restrict__ b_rel2,
                           const float* __restrict__ W_a,
                           const float* __restrict__ b_a) {
    int r = blockIdx.x * 4 + (threadIdx.x >> 5);
    int lane = threadIdx.x & 31;
    if (r >= RR) return;
    float x0 = rel_embed[r * DD + lane];
    float x1 = rel_embed[r * DD + 32 + lane];
    int i0 = lane, i1 = lane + 32;
    float rl0 = b_relL[i0], rl1 = b_relL[i1];
    float p0 = g_c0[i0], p1 = g_c0[i1];
#pragma unroll
    for (int k = 0; k < DD; k++) {
        float xk = (k < 32) ? __shfl_sync(0xffffffffu, x0, k)
                            : __shfl_sync(0xffffffffu, x1, k - 32);
        rl0 = fmaf(xk, W_relL[i0 * DD + k], rl0);
        rl1 = fmaf(xk, W_relL[i1 * DD + k], rl1);
        p0  = fmaf(xk, g_M3[i0 * DD + k], p0);
        p1  = fmaf(xk, g_M3[i1 * DD + k], p1);
    }
    g_P3p[r * DD + i0] = p0;
    g_P3p[r * DD + i1] = p1;
    float r20 = b_rel2[i0], r21 = b_rel2[i1];
#pragma unroll
    for (int k = 0; k < DD; k++) {
        float rk = (k < 32) ? __shfl_sync(0xffffffffu, rl0, k)
                            : __shfl_sync(0xffffffffu, rl1, k - 32);
        r20 = fmaf(rk, W_rel2[i0 * DD + k], r20);
        r21 = fmaf(rk, W_rel2[i1 * DD + k], r21);
    }
    g_R2[r * DD + i0] = r20;
    g_R2[r * DD + i1] = r21;
    float q = fmaf(p0, W_a[i0], p1 * W_a[i1]);
#pragma unroll
    for (int o = 16; o > 0; o >>= 1) q += __shfl_xor_sync(0xffffffffu, q, o);
    if (lane == 0) g_q3[r] = q + b_a[0];
}

// ---------------- 3. node tables: P1, P2, q1, q2 -----------------------------
__global__ void __launch_bounds__(128) k_node_proj(const float* __restrict__ ent,
                                                   const float* __restrict__ W_a) {
    __shared__ float sM1[DD * DD];
    __shared__ float sM2[DD * DD];
    __shared__ float sA[DD];
    for (int idx = threadIdx.x; idx < DD * DD; idx += 128) {
        sM1[idx] = g_M1[idx];
        sM2[idx] = g_M2[idx];
    }
    if (threadIdx.x < DD) sA[threadIdx.x] = W_a[threadIdx.x];
    __syncthreads();

    int node = blockIdx.x * 128 + threadIdx.x;
    if (node >= NN) return;

    float xs[DD];
    const float4* xr = (const float4*)(ent + node * DD);
#pragma unroll
    for (int u = 0; u < 16; u++) {
        float4 v = xr[u];
        xs[4 * u + 0] = v.x; xs[4 * u + 1] = v.y;
        xs[4 * u + 2] = v.z; xs[4 * u + 3] = v.w;
    }
    float q1a = 0.f;
#pragma unroll 1
    for (int i = 0; i < DD; i += 4) {
        float a0 = 0.f, a1 = 0.f, a2 = 0.f, a3 = 0.f;
#pragma unroll
        for (int k = 0; k < DD; k++) {
            float xk = xs[k];
            a0 = fmaf(xk, sM1[(i + 0) * DD + k], a0);
            a1 = fmaf(xk, sM1[(i + 1) * DD + k], a1);
            a2 = fmaf(xk, sM1[(i + 2) * DD + k], a2);
            a3 = fmaf(xk, sM1[(i + 3) * DD + k], a3);
        }
        float4 v = make_float4(a0, a1, a2, a3);
        *(float4*)&g_P1[node * DD + i] = v;
        q1a = fmaf(a0, sA[i], q1a); q1a = fmaf(a1, sA[i + 1], q1a);
        q1a = fmaf(a2, sA[i + 2], q1a); q1a = fmaf(a3, sA[i + 3], q1a);
    }
    g_q1[node] = q1a;

    float q2a = 0.f;
#pragma unroll 1
    for (int i = 0; i < DD; i += 4) {
        float a0 = 0.f, a1 = 0.f, a2 = 0.f, a3 = 0.f;
#pragma unroll
        for (int k = 0; k < DD; k++) {
            float xk = xs[k];
            a0 = fmaf(xk, sM2[(i + 0) * DD + k], a0);
            a1 = fmaf(xk, sM2[(i + 1) * DD + k], a1);
            a2 = fmaf(xk, sM2[(i + 2) * DD + k], a2);
            a3 = fmaf(xk, sM2[(i + 3) * DD + k], a3);
        }
        float4 v = make_float4(a0, a1, a2, a3);
        *(float4*)&g_P2[node * DD + i] = v;
        q2a = fmaf(a0, sA[i], q2a); q2a = fmaf(a1, sA[i + 1], q2a);
        q2a = fmaf(a2, sA[i + 2], q2a); q2a = fmaf(a3, sA[i + 3], q2a);
    }
    g_q2[node] = q2a;
}

// ---------------- 4. per-edge: exp(leaky(logit)) + bin counts ----------------
// 4 edges/thread (int4 loads), padded rel counters.
__global__ void __launch_bounds__(256) k_edge_pre(const int4* __restrict__ src4,
                                                  const int4* __restrict__ dst4,
                                                  const int4* __restrict__ rel4) {
    int t = blockIdx.x * blockDim.x + threadIdx.x;
    if (t >= EE / 4) return;
    int4 s = src4[t], d = dst4[t], r = rel4[t];
    float q1x = g_q1[s.x], q1y = g_q1[s.y], q1z = g_q1[s.z], q1w = g_q1[s.w];
    float q2x = g_q2[d.x], q2y = g_q2[d.y], q2z = g_q2[d.z], q2w = g_q2[d.w];
    float q3x = g_q3[r.x], q3y = g_q3[r.y], q3z = g_q3[r.z], q3w = g_q3[r.w];
    float lx = q1x + q2x + q3x;
    float ly = q1y + q2y + q3y;
    float lz = q1z + q2z + q3z;
    float lw = q1w + q2w + q3w;
    lx = (lx >= 0.f) ? lx : 0.01f * lx;
    ly = (ly >= 0.f) ? ly : 0.01f * ly;
    lz = (lz >= 0.f) ? lz : 0.01f * lz;
    lw = (lw >= 0.f) ? lw : 0.01f * lw;
    float4 o = make_float4(expf(lx), expf(ly), expf(lz), expf(lw));
    ((float4*)g_bexp)[t] = o;
    atomicAdd(&g_src_cnt[s.x], 1);
    atomicAdd(&g_src_cnt[s.y], 1);
    atomicAdd(&g_src_cnt[s.z], 1);
    atomicAdd(&g_src_cnt[s.w], 1);
    atomicAdd(&g_rel_cnt[r.x * RPAD], 1);
    atomicAdd(&g_rel_cnt[r.y * RPAD], 1);
    atomicAdd(&g_rel_cnt[r.z * RPAD], 1);
    atomicAdd(&g_rel_cnt[r.w * RPAD], 1);
}

// ---------------- 5. scans / CSR build ---------------------------------------
__global__ void k_scan1() {
    __shared__ int ws[32];
    int i = blockIdx.x * 1024 + threadIdx.x;
    int v = (i < NN) ? g_src_cnt[i] : 0;
    int lane = threadIdx.x & 31, wid = threadIdx.x >> 5;
#pragma unroll
    for (int o = 16; o > 0; o >>= 1) v += __shfl_down_sync(0xffffffffu, v, o);
    if (lane == 0) ws[wid] = v;
    __syncthreads();
    if (wid == 0) {
        int s = ws[lane];
#pragma unroll
        for (int o = 16; o > 0; o >>= 1) s += __shfl_down_sync(0xffffffffu, s, o);
        if (lane == 0) g_blocksum[blockIdx.x] = s;
    }
}
__global__ void k_scan2() {
    __shared__ int ws[32];
    int v = (threadIdx.x < NB_N) ? g_blocksum[threadIdx.x] : 0;
    int ex = blockExScan(v, ws);
    if (threadIdx.x < NB_N) g_blocksum[threadIdx.x] = ex;
    if (threadIdx.x == 0) g_src_off[NN] = EE;
}
__global__ void k_scan3() {
    __shared__ int ws[32];
    int i = blockIdx.x * 1024 + threadIdx.x;
    int v = (i < NN) ? g_src_cnt[i] : 0;
    int ex = blockExScan(v, ws) + g_blocksum[blockIdx.x];
    if (i < NN) { g_src_off[i] = ex; g_src_cur[i] = ex; }
}
__global__ void k_relscan() {
    __shared__ int ws[32];
    int i = threadIdx.x;
    int v = (i < RR) ? g_rel_cnt[i * RPAD] : 0;
    int ex = blockExScan(v, ws);
    if (i < RR) { g_rel_off[i] = ex; g_rel_cur[i * RPAD] = ex; }
    if (i == 0) g_rel_off[RR] = EE;
}
__global__ void __launch_bounds__(256) k_fill(const int4* __restrict__ src4,
                                              const int4* __restrict__ rel4) {
    int t = blockIdx.x * blockDim.x + threadIdx.x;
    if (t >= EE / 4) return;
    int4 s = src4[t], r = rel4[t];
    int e0 = 4 * t, e1 = 4 * t + 1, e2 = 4 * t + 2, e3 = 4 * t + 3;
    g_src_edges[atomicAdd(&g_src_cur[s.x], 1)] = e0;
    g_src_edges[atomicAdd(&g_src_cur[s.y], 1)] = e1;
    g_src_edges[atomicAdd(&g_src_cur[s.z], 1)] = e2;
    g_src_edges[atomicAdd(&g_src_cur[s.w], 1)] = e3;
    g_rel_edges[atomicAdd(&g_rel_cur[r.x * RPAD], 1)] = e0;
    g_rel_edges[atomicAdd(&g_rel_cur[r.y * RPAD], 1)] = e1;
    g_rel_edges[atomicAdd(&g_rel_cur[r.z * RPAD], 1)] = e2;
    g_rel_edges[atomicAdd(&g_rel_cur[r.w * RPAD], 1)] = e3;
}

// ---------------- 6. node aggregation: h_ent ---------------------------------
__global__ void __launch_bounds__(256) k_node_agg(const int* __restrict__ dst,
                                                  const int* __restrict__ rel,
                                                  float* __restrict__ out) {
    int wid = threadIdx.x >> 5;
    int lane = threadIdx.x & 31;
    int n = blockIdx.x * 8 + wid;
    if (n >= NN) return;
    int j0 = g_src_off[n];
    int j1 = g_src_off[n + 1];
    int j = j0;
    float acc0 = 0.f, acc1 = 0.f, bsum = 0.f;
    for (; j + 4 <= j1; j += 4) {
        int eA = g_src_edges[j], eB = g_src_edges[j + 1];
        int eC = g_src_edges[j + 2], eD = g_src_edges[j + 3];
        int dA = dst[eA], rA = rel[eA];
        int dB = dst[eB], rB = rel[eB];
        int dC = dst[eC], rC = rel[eC];
        int dD = dst[eD], rD = rel[eD];
        float bA = g_bexp[eA], bB = g_bexp[eB], bC = g_bexp[eC], bD = g_bexp[eD];
        float pA0 = g_P2[dA * DD + lane],      qA0 = g_P3p[rA * DD + lane];
        float pA1 = g_P2[dA * DD + 32 + lane], qA1 = g_P3p[rA * DD + 32 + lane];
        float pB0 = g_P2[dB * DD + lane],      qB0 = g_P3p[rB * DD + lane];
        float pB1 = g_P2[dB * DD + 32 + lane], qB1 = g_P3p[rB * DD + 32 + lane];
        float pC0 = g_P2[dC * DD + lane],      qC0 = g_P3p[rC * DD + lane];
        float pC1 = g_P2[dC * DD + 32 + lane], qC1 = g_P3p[rC * DD + 32 + lane];
        float pD0 = g_P2[dD * DD + lane],      qD0 = g_P3p[rD * DD + lane];
        float pD1 = g_P2[dD * DD + 32 + lane], qD1 = g_P3p[rD * DD + 32 + lane];
        acc0 = fmaf(bA, pA0 + qA0, acc0); acc1 = fmaf(bA, pA1 + qA1, acc1);
        acc0 = fmaf(bB, pB0 + qB0, acc0); acc1 = fmaf(bB, pB1 + qB1, acc1);
        acc0 = fmaf(bC, pC0 + qC0, acc0); acc1 = fmaf(bC, pC1 + qC1, acc1);
        acc0 = fmaf(bD, pD0 + qD0, acc0); acc1 = fmaf(bD, pD1 + qD1, acc1);
        bsum += (bA + bB) + (bC + bD);
    }
    for (; j < j1; j++) {
        int e = g_src_edges[j];
        int d = dst[e], r = rel[e];
        float b = g_bexp[e];
        acc0 = fmaf(b, g_P2[d * DD + lane] + g_P3p[r * DD + lane], acc0);
        acc1 = fmaf(b, g_P2[d * DD + 32 + lane] + g_P3p[r * DD + 32 + lane], acc1);
        bsum += b;
    }
    float h0, h1;
    if (j1 > j0) {
        float inv = 1.f / bsum;
        h0 = g_P1[n * DD + lane] + acc0 * inv;
        h1 = g_P1[n * DD + 32 + lane] + acc1 * inv;
    } else {
        h0 = 0.f; h1 = 0.f;
    }
    out[n * DD + lane] = h0;
    out[n * DD + 32 + lane] = h1;
}

// ---------------- 7. relation pooling sums -----------------------------------
__global__ void __launch_bounds__(128) k_rel_pool(const int* __restrict__ src,
                                                  const int* __restrict__ dst,
                                                  const float* __restrict__ h) {
    int r = blockIdx.x >> 3;
    int part = blockIdx.x & (SPLIT - 1);
    int b0 = g_rel_off[r], b1 = g_rel_off[r + 1];
    int len = b1 - b0;
    int per = (len + SPLIT - 1) >> 3;
    int j0 = b0 + part * per;
    int j1 = min(j0 + per, b1);
    if (j0 >= j1) return;
    int t = threadIdx.x;
    bool isSrc = (t < 64);
    int dim = isSrc ? t : (t - 64);
    const int* nodeArr = isSrc ? src : dst;
    float acc = 0.f;
    int j = j0;
    for (; j + 4 <= j1; j += 4) {
        int e0 = g_rel_edges[j + 0], e1 = g_rel_edges[j + 1];
        int e2 = g_rel_edges[j + 2], e3 = g_rel_edges[j + 3];
        int n0 = nodeArr[e0], n1 = nodeArr[e1], n2 = nodeArr[e2], n3 = nodeArr[e3];
        float v0 = h[n0 * DD + dim];
        float v1 = h[n1 * DD + dim];
        float v2 = h[n2 * DD + dim];
        float v3 = h[n3 * DD + dim];
        acc += (v0 + v1) + (v2 + v3);
    }
    for (; j < j1; j++) {
        int e = g_rel_edges[j];
        acc += h[nodeArr[e] * DD + dim];
    }
    atomicAdd(&g_relsum[r * 128 + t], acc);
}

// ---------------- 8. h_rel = mean @ W_rel3^T + b_rel3 ------------------------
__global__ void k_rel_out(const float* __restrict__ W_rel3,
                          const float* __restrict__ b_rel3,
                          float* __restrict__ out) {
    int r = blockIdx.x * 4 + (threadIdx.x >> 5);
    int lane = threadIdx.x & 31;
    if (r >= RR) return;
    int cnt = g_rel_off[r + 1] - g_rel_off[r];
    float inv = 1.f / (float)max(cnt, 1);
    int i0 = lane, i1 = lane + 32;
    float h0 = b_rel3[i0], h1 = b_rel3[i1];
#pragma unroll 4
    for (int jj = 0; jj < 128; jj++) {
        float m = g_relsum[r * 128 + jj] * inv;
        h0 = fmaf(W_rel3[i0 * 192 + jj], m, h0);
        h1 = fmaf(W_rel3[i1 * 192 + jj], m, h1);
    }
#pragma unroll 4
    for (int jj = 0; jj < 64; jj++) {
        float m = g_R2[r * DD + jj];
        h0 = fmaf(W_rel3[i0 * 192 + 128 + jj], m, h0);
        h1 = fmaf(W_rel3[i1 * 192 + 128 + jj], m, h1);
    }
    out[NN * DD + r * DD + i0] = h0;
    out[NN * DD + r * DD + i1] = h1;
}

// ---------------- launcher ---------------------------------------------------
extern "C" void kernel_launch(void* const* d_in, const int* in_sizes, int n_in,
                              void* d_out, int out_size) {
    const float* ent_embed = (const float*)d_in[0];
    const float* rel_embed = (const float*)d_in[1];
    const float* W_ent  = (const float*)d_in[2];
    const float* b_ent  = (const float*)d_in[3];
    const float* W_relL = (const float*)d_in[4];
    const float* b_relL = (const float*)d_in[5];
    const float* W_rel2 = (const float*)d_in[6];
    const float* b_rel2 = (const float*)d_in[7];
    const float* W_rel3 = (const float*)d_in[8];
    const float* b_rel3 = (const float*)d_in[9];
    const float* W_a    = (const float*)d_in[10];
    const float* b_a    = (const float*)d_in[11];
    const float* W_fc   = (const float*)d_in[12];
    const float* b_fc   = (const float*)d_in[13];
    const int* src_idx = (const int*)d_in[14];
    const int* dst_idx = (const int*)d_in[15];
    const int* rel_idx = (const int*)d_in[16];
    float* out = (float*)d_out;

    void *pSrcCnt, *pRelCnt, *pRelSum;
    cudaGetSymbolAddress(&pSrcCnt, g_src_cnt);
    cudaGetSymbolAddress(&pRelCnt, g_rel_cnt);
    cudaGetSymbolAddress(&pRelSum, g_relsum);
    cudaMemsetAsync(pSrcCnt, 0, NN * sizeof(int), 0);
    cudaMemsetAsync(pRelCnt, 0, RR * RPAD * sizeof(int), 0);
    cudaMemsetAsync(pRelSum, 0, RR * 128 * sizeof(float), 0);

    k_precompute<<<1, 256>>>(W_ent, W_relL, W_fc, b_ent, b_relL, b_fc);
    k_rel_proj<<<(RR + 3) / 4, 128>>>(rel_embed, W_relL, b_relL, W_rel2, b_rel2, W_a, b_a);
    k_node_proj<<<(NN + 127) / 128, 128>>>(ent_embed, W_a);
    k_edge_pre<<<(EE / 4 + 255) / 256, 256>>>((const int4*)src_idx,
                                              (const int4*)dst_idx,
                                              (const int4*)rel_idx);
    k_scan1<<<NB_N, 1024>>>();
    k_scan2<<<1, 128>>>();
    k_scan3<<<NB_N, 1024>>>();
    k_relscan<<<1, 512>>>();
    k_fill<<<(EE / 4 + 255) / 256, 256>>>((const int4*)src_idx, (const int4*)rel_idx);
    k_node_agg<<<(NN + 7) / 8, 256>>>(dst_idx, rel_idx, out);
    k_rel_pool<<<RR * SPLIT, 128>>>(src_idx, dst_idx, out);
    k_rel_out<<<(RR + 3) / 4, 128>>>(W_rel3, b_rel3, out);
}

// round 3
// speedup vs baseline: 1.8505x; 1.1537x over previous
#include <cuda_runtime.h>
#include <cuda_bf16.h>
#include <math.h>

#define NN 100000
#define EE 1000000
#define RR 500
#define DD 64
#define NB_N 98            // ceil(100000/1024)
#define SPLIT 8
#define RPAD 32            // 128B stride for relation counters

// ---------------- scratch (device globals) ------------------------------------
__device__ __align__(16) float g_P1[NN * DD];
__device__ __align__(16) float g_P2[NN * DD];
__device__ float g_q1[NN];
__device__ float g_q2[NN];
__device__ __align__(16) float g_P3p[RR * DD];
__device__ float g_q3[RR];
__device__ float g_R2[RR * DD];
__device__ float g_M1[DD * DD];
__device__ float g_M2[DD * DD];
__device__ float g_M3[DD * DD];
__device__ float g_c0[DD];
__device__ float g_bexp[EE];
__device__ int   g_src_cnt[NN];
__device__ int   g_rel_cnt[RR * RPAD];
__device__ int   g_src_off[NN + 1];
__device__ int   g_rel_off[RR + 1];
__device__ int   g_src_cur[NN];
__device__ int   g_rel_cur[RR * RPAD];
__device__ int   g_src_edges[EE];
__device__ int   g_rel_edges[EE];
__device__ int   g_blocksum[128];
__device__ float g_relsum[RR * 128];

// ---------------- helpers ----------------------------------------------------
__device__ __forceinline__ int blockExScan(int v, int* warpSums) {
    int lane = threadIdx.x & 31;
    int wid  = threadIdx.x >> 5;
    int nw   = blockDim.x >> 5;
    int inc = v;
#pragma unroll
    for (int o = 1; o < 32; o <<= 1) {
        int t = __shfl_up_sync(0xffffffffu, inc, o);
        if (lane >= o) inc += t;
    }
    if (lane == 31) warpSums[wid] = inc;
    __syncthreads();
    if (wid == 0) {
        int w = (lane < nw) ? warpSums[lane] : 0;
#pragma unroll
        for (int o = 1; o < 32; o <<= 1) {
            int t = __shfl_up_sync(0xffffffffu, w, o);
            if (lane >= o) w += t;
        }
        if (lane < nw) warpSums[lane] = w;
    }
    __syncthreads();
    int base = (wid > 0) ? warpSums[wid - 1] : 0;
    return base + inc - v;   // exclusive
}

// ---------------- 1. composed weight matrices --------------------------------
__global__ void k_precompute(const float* __restrict__ W_ent,
                             const float* __restrict__ W_relL,
                             const float* __restrict__ W_fc,
                             const float* __restrict__ b_ent,
                             const float* __restrict__ b_relL,
                             const float* __restrict__ b_fc) {
    int tid = threadIdx.x;
    for (int idx = tid; idx < DD * DD; idx += blockDim.x) {
        int i = idx >> 6, j = idx & 63;
        float a1 = 0.f, a2 = 0.f, a3 = 0.f;
#pragma unroll 8
        for (int k = 0; k < DD; k++) {
            float e = W_ent[k * DD + j];
            a1 = fmaf(W_fc[i * 192 + k], e, a1);
            a2 = fmaf(W_fc[i * 192 + 64 + k], e, a2);
            a3 = fmaf(W_fc[i * 192 + 128 + k], W_relL[k * DD + j], a3);
        }
        g_M1[idx] = a1; g_M2[idx] = a2; g_M3[idx] = a3;
    }
    if (tid < DD) {
        float c = b_fc[tid];
#pragma unroll 8
        for (int k = 0; k < DD; k++) {
            c = fmaf(W_fc[tid * 192 + k], b_ent[k], c);
            c = fmaf(W_fc[tid * 192 + 64 + k], b_ent[k], c);
            c = fmaf(W_fc[tid * 192 + 128 + k], b_relL[k], c);
        }
        g_c0[tid] = c;
    }
}

// ---------------- 2. relation tables: P3p, q3, R2 ----------------------------
__global__ void k_rel_proj(const float* __restrict__ rel_embed,
                           const float* __restrict__ W_relL,
                           const float* __restrict__ b_relL,
                           const float* __restrict__ W_rel2,
                           const float* __restrict__ b_rel2,
                           const float* __restrict__ W_a,
                           const float* __restrict__ b_a) {
    int r = blockIdx.x * 4 + (threadIdx.x >> 5);
    int lane = threadIdx.x & 31;
    if (r >= RR) return;
    float x0 = rel_embed[r * DD + lane];
    float x1 = rel_embed[r * DD + 32 + lane];
    int i0 = lane, i1 = lane + 32;
    float rl0 = b_relL[i0], rl1 = b_relL[i1];
    float p0 = g_c0[i0], p1 = g_c0[i1];
#pragma unroll
    for (int k = 0; k < DD; k++) {
        float xk = (k < 32) ? __shfl_sync(0xffffffffu, x0, k)
                            : __shfl_sync(0xffffffffu, x1, k - 32);
        rl0 = fmaf(xk, W_relL[i0 * DD + k], rl0);
        rl1 = fmaf(xk, W_relL[i1 * DD + k], rl1);
        p0  = fmaf(xk, g_M3[i0 * DD + k], p0);
        p1  = fmaf(xk, g_M3[i1 * DD + k], p1);
    }
    g_P3p[r * DD + i0] = p0;
    g_P3p[r * DD + i1] = p1;
    float r20 = b_rel2[i0], r21 = b_rel2[i1];
#pragma unroll
    for (int k = 0; k < DD; k++) {
        float rk = (k < 32) ? __shfl_sync(0xffffffffu, rl0, k)
                            : __shfl_sync(0xffffffffu, rl1, k - 32);
        r20 = fmaf(rk, W_rel2[i0 * DD + k], r20);
        r21 = fmaf(rk, W_rel2[i1 * DD + k], r21);
    }
    g_R2[r * DD + i0] = r20;
    g_R2[r * DD + i1] = r21;
    float q = fmaf(p0, W_a[i0], p1 * W_a[i1]);
#pragma unroll
    for (int o = 16; o > 0; o >>= 1) q += __shfl_xor_sync(0xffffffffu, q, o);
    if (lane == 0) g_q3[r] = q + b_a[0];
}

// ---------------- 3. node tables: P1, P2, q1, q2 -----------------------------
__global__ void __launch_bounds__(128) k_node_proj(const float* __restrict__ ent,
                                                   const float* __restrict__ W_a) {
    __shared__ float sM1[DD * DD];
    __shared__ float sM2[DD * DD];
    __shared__ float sA[DD];
    for (int idx = threadIdx.x; idx < DD * DD; idx += 128) {
        sM1[idx] = g_M1[idx];
        sM2[idx] = g_M2[idx];
    }
    if (threadIdx.x < DD) sA[threadIdx.x] = W_a[threadIdx.x];
    __syncthreads();

    int node = blockIdx.x * 128 + threadIdx.x;
    if (node >= NN) return;

    float xs[DD];
    const float4* xr = (const float4*)(ent + node * DD);
#pragma unroll
    for (int u = 0; u < 16; u++) {
        float4 v = xr[u];
        xs[4 * u + 0] = v.x; xs[4 * u + 1] = v.y;
        xs[4 * u + 2] = v.z; xs[4 * u + 3] = v.w;
    }
    float q1a = 0.f;
#pragma unroll 1
    for (int i = 0; i < DD; i += 4) {
        float a0 = 0.f, a1 = 0.f, a2 = 0.f, a3 = 0.f;
#pragma unroll
        for (int k = 0; k < DD; k++) {
            float xk = xs[k];
            a0 = fmaf(xk, sM1[(i + 0) * DD + k], a0);
            a1 = fmaf(xk, sM1[(i + 1) * DD + k], a1);
            a2 = fmaf(xk, sM1[(i + 2) * DD + k], a2);
            a3 = fmaf(xk, sM1[(i + 3) * DD + k], a3);
        }
        float4 v = make_float4(a0, a1, a2, a3);
        *(float4*)&g_P1[node * DD + i] = v;
        q1a = fmaf(a0, sA[i], q1a); q1a = fmaf(a1, sA[i + 1], q1a);
        q1a = fmaf(a2, sA[i + 2], q1a); q1a = fmaf(a3, sA[i + 3], q1a);
    }
    g_q1[node] = q1a;

    float q2a = 0.f;
#pragma unroll 1
    for (int i = 0; i < DD; i += 4) {
        float a0 = 0.f, a1 = 0.f, a2 = 0.f, a3 = 0.f;
#pragma unroll
        for (int k = 0; k < DD; k++) {
            float xk = xs[k];
            a0 = fmaf(xk, sM2[(i + 0) * DD + k], a0);
            a1 = fmaf(xk, sM2[(i + 1) * DD + k], a1);
            a2 = fmaf(xk, sM2[(i + 2) * DD + k], a2);
            a3 = fmaf(xk, sM2[(i + 3) * DD + k], a3);
        }
        float4 v = make_float4(a0, a1, a2, a3);
        *(float4*)&g_P2[node * DD + i] = v;
        q2a = fmaf(a0, sA[i], q2a); q2a = fmaf(a1, sA[i + 1], q2a);
        q2a = fmaf(a2, sA[i + 2], q2a); q2a = fmaf(a3, sA[i + 3], q2a);
    }
    g_q2[node] = q2a;
}

// ---------------- 4a. counts (side stream) -----------------------------------
__global__ void __launch_bounds__(256) k_count(const int4* __restrict__ src4,
                                               const int4* __restrict__ rel4) {
    int t = blockIdx.x * blockDim.x + threadIdx.x;
    if (t >= EE / 4) return;
    int4 s = src4[t], r = rel4[t];
    atomicAdd(&g_src_cnt[s.x], 1);
    atomicAdd(&g_src_cnt[s.y], 1);
    atomicAdd(&g_src_cnt[s.z], 1);
    atomicAdd(&g_src_cnt[s.w], 1);
    atomicAdd(&g_rel_cnt[r.x * RPAD], 1);
    atomicAdd(&g_rel_cnt[r.y * RPAD], 1);
    atomicAdd(&g_rel_cnt[r.z * RPAD], 1);
    atomicAdd(&g_rel_cnt[r.w * RPAD], 1);
}

// ---------------- 4b. per-edge logits -> exp (main stream) -------------------
__global__ void __launch_bounds__(256) k_edge_logits(const int4* __restrict__ src4,
                                                     const int4* __restrict__ dst4,
                                                     const int4* __restrict__ rel4) {
    int t = blockIdx.x * blockDim.x + threadIdx.x;
    if (t >= EE / 4) return;
    int4 s = src4[t], d = dst4[t], r = rel4[t];
    float lx = g_q1[s.x] + g_q2[d.x] + g_q3[r.x];
    float ly = g_q1[s.y] + g_q2[d.y] + g_q3[r.y];
    float lz = g_q1[s.z] + g_q2[d.z] + g_q3[r.z];
    float lw = g_q1[s.w] + g_q2[d.w] + g_q3[r.w];
    lx = (lx >= 0.f) ? lx : 0.01f * lx;
    ly = (ly >= 0.f) ? ly : 0.01f * ly;
    lz = (lz >= 0.f) ? lz : 0.01f * lz;
    lw = (lw >= 0.f) ? lw : 0.01f * lw;
    ((float4*)g_bexp)[t] = make_float4(expf(lx), expf(ly), expf(lz), expf(lw));
}

// ---------------- 5. scans / CSR build ---------------------------------------
__global__ void k_scan1() {
    __shared__ int ws[32];
    int i = blockIdx.x * 1024 + threadIdx.x;
    int v = (i < NN) ? g_src_cnt[i] : 0;
    int lane = threadIdx.x & 31, wid = threadIdx.x >> 5;
#pragma unroll
    for (int o = 16; o > 0; o >>= 1) v += __shfl_down_sync(0xffffffffu, v, o);
    if (lane == 0) ws[wid] = v;
    __syncthreads();
    if (wid == 0) {
        int s = ws[lane];
#pragma unroll
        for (int o = 16; o > 0; o >>= 1) s += __shfl_down_sync(0xffffffffu, s, o);
        if (lane == 0) g_blocksum[blockIdx.x] = s;
    }
}
__global__ void k_scan2() {
    __shared__ int ws[32];
    int v = (threadIdx.x < NB_N) ? g_blocksum[threadIdx.x] : 0;
    int ex = blockExScan(v, ws);
    if (threadIdx.x < NB_N) g_blocksum[threadIdx.x] = ex;
    if (threadIdx.x == 0) g_src_off[NN] = EE;
}
__global__ void k_scan3() {
    __shared__ int ws[32];
    int i = blockIdx.x * 1024 + threadIdx.x;
    int v = (i < NN) ? g_src_cnt[i] : 0;
    int ex = blockExScan(v, ws) + g_blocksum[blockIdx.x];
    if (i < NN) { g_src_off[i] = ex; g_src_cur[i] = ex; }
}
__global__ void k_relscan() {
    __shared__ int ws[32];
    int i = threadIdx.x;
    int v = (i < RR) ? g_rel_cnt[i * RPAD] : 0;
    int ex = blockExScan(v, ws);
    if (i < RR) { g_rel_off[i] = ex; g_rel_cur[i * RPAD] = ex; }
    if (i == 0) g_rel_off[RR] = EE;
}
__global__ void __launch_bounds__(256) k_fill(const int4* __restrict__ src4,
                                              const int4* __restrict__ rel4) {
    int t = blockIdx.x * blockDim.x + threadIdx.x;
    if (t >= EE / 4) return;
    int4 s = src4[t], r = rel4[t];
    int e0 = 4 * t, e1 = 4 * t + 1, e2 = 4 * t + 2, e3 = 4 * t + 3;
    g_src_edges[atomicAdd(&g_src_cur[s.x], 1)] = e0;
    g_src_edges[atomicAdd(&g_src_cur[s.y], 1)] = e1;
    g_src_edges[atomicAdd(&g_src_cur[s.z], 1)] = e2;
    g_src_edges[atomicAdd(&g_src_cur[s.w], 1)] = e3;
    g_rel_edges[atomicAdd(&g_rel_cur[r.x * RPAD], 1)] = e0;
    g_rel_edges[atomicAdd(&g_rel_cur[r.y * RPAD], 1)] = e1;
    g_rel_edges[atomicAdd(&g_rel_cur[r.z * RPAD], 1)] = e2;
    g_rel_edges[atomicAdd(&g_rel_cur[r.w * RPAD], 1)] = e3;
}

// ---------------- 6. node aggregation: h_ent (float4, half-warp per edge) ----
__global__ void __launch_bounds__(256) k_node_agg(const int* __restrict__ dst,
                                                  const int* __restrict__ rel,
                                                  float* __restrict__ out) {
    const float4* P1 = (const float4*)g_P1;
    const float4* P2 = (const float4*)g_P2;
    const float4* P3 = (const float4*)g_P3p;
    int wid = threadIdx.x >> 5;
    int lane = threadIdx.x & 31;
    int n = blockIdx.x * 8 + wid;
    if (n >= NN) return;
    int j0 = g_src_off[n];
    int j1 = g_src_off[n + 1];
    int half = lane >> 4;          // which edge of the pair
    int q = lane & 15;             // dim quad
    float4 acc = make_float4(0.f, 0.f, 0.f, 0.f);
    float bsum = 0.f;
    int j = j0 + half;
    for (; j + 2 < j1; j += 4) {   // 2 edges per half per iter
        int eA = g_src_edges[j];
        int eB = g_src_edges[j + 2];
        int dA = dst[eA], rA = rel[eA];
        int dB = dst[eB], rB = rel[eB];
        float bA = g_bexp[eA], bB = g_bexp[eB];
        float4 pA = P2[dA * 16 + q];
        float4 tA = P3[rA * 16 + q];
        float4 pB = P2[dB * 16 + q];
        float4 tB = P3[rB * 16 + q];
        acc.x = fmaf(bA, pA.x + tA.x, acc.x); acc.x = fmaf(bB, pB.x + tB.x, acc.x);
        acc.y = fmaf(bA, pA.y + tA.y, acc.y); acc.y = fmaf(bB, pB.y + tB.y, acc.y);
        acc.z = fmaf(bA, pA.z + tA.z, acc.z); acc.z = fmaf(bB, pB.z + tB.z, acc.z);
        acc.w = fmaf(bA, pA.w + tA.w, acc.w); acc.w = fmaf(bB, pB.w + tB.w, acc.w);
        bsum += bA + bB;
    }
    if (j < j1) {
        int e = g_src_edges[j];
        int d = dst[e], r = rel[e];
        float b = g_bexp[e];
        float4 p = P2[d * 16 + q];
        float4 tq = P3[r * 16 + q];
        acc.x = fmaf(b, p.x + tq.x, acc.x);
        acc.y = fmaf(b, p.y + tq.y, acc.y);
        acc.z = fmaf(b, p.z + tq.z, acc.z);
        acc.w = fmaf(b, p.w + tq.w, acc.w);
        bsum += b;
    }
    // combine the two half-warps (lane i += lane i+16)
    acc.x += __shfl_down_sync(0xffffffffu, acc.x, 16);
    acc.y += __shfl_down_sync(0xffffffffu, acc.y, 16);
    acc.z += __shfl_down_sync(0xffffffffu, acc.z, 16);
    acc.w += __shfl_down_sync(0xffffffffu, acc.w, 16);
    bsum  += __shfl_down_sync(0xffffffffu, bsum, 16);
    if (half == 0) {
        float4 h;
        if (j1 > j0) {
            float inv = 1.f / bsum;
            float4 p1 = P1[n * 16 + q];
            h.x = p1.x + acc.x * inv;
            h.y = p1.y + acc.y * inv;
            h.z = p1.z + acc.z * inv;
            h.w = p1.w + acc.w * inv;
        } else {
            h = make_float4(0.f, 0.f, 0.f, 0.f);
        }
        ((float4*)out)[n * 16 + q] = h;
    }
}

// ---------------- 7. relation pooling sums (float4) --------------------------
__global__ void __launch_bounds__(128) k_rel_pool(const int* __restrict__ src,
                                                  const int* __restrict__ dst,
                                                  const float4* __restrict__ h4) {
    __shared__ float4 sred[4][32];
    int r = blockIdx.x >> 3;
    int part = blockIdx.x & (SPLIT - 1);
    int b0 = g_rel_off[r], b1 = g_rel_off[r + 1];
    int len = b1 - b0;
    int per = (len + SPLIT - 1) >> 3;
    int j0 = b0 + part * per;
    int j1 = min(j0 + per, b1);
    int t = threadIdx.x;
    int eslot = t >> 5;            // 0..3
    int lane = t & 31;
    int isDst = lane >> 4;
    int q = lane & 15;
    const int* nodeArr = isDst ? dst : src;
    float4 acc = make_float4(0.f, 0.f, 0.f, 0.f);
    int j = j0 + eslot;
    for (; j + 4 < j1; j += 8) {   // 2 edges per slot per iter
        int eA = g_rel_edges[j];
        int eB = g_rel_edges[j + 4];
        int nA = nodeArr[eA];
        int nB = nodeArr[eB];
        float4 vA = h4[nA * 16 + q];
        float4 vB = h4[nB * 16 + q];
        acc.x += vA.x + vB.x;
        acc.y += vA.y + vB.y;
        acc.z += vA.z + vB.z;
        acc.w += vA.w + vB.w;
    }
    if (j < j1) {
        int e = g_rel_edges[j];
        int n = nodeArr[e];
        float4 v = h4[n * 16 + q];
        acc.x += v.x; acc.y += v.y; acc.z += v.z; acc.w += v.w;
    }
    sred[eslot][lane] = acc;
    __syncthreads();
    if (eslot == 0) {
        float4 a = sred[0][lane], b = sred[1][lane], c = sred[2][lane], d = sred[3][lane];
        float sx = (a.x + b.x) + (c.x + d.x);
        float sy = (a.y + b.y) + (c.y + d.y);
        float sz = (a.z + b.z) + (c.z + d.z);
        float sw = (a.w + b.w) + (c.w + d.w);
        int base = r * 128 + isDst * 64 + q * 4;
        atomicAdd(&g_relsum[base + 0], sx);
        atomicAdd(&g_relsum[base + 1], sy);
        atomicAdd(&g_relsum[base + 2], sz);
        atomicAdd(&g_relsum[base + 3], sw);
    }
}

// ---------------- 8. h_rel = mean @ W_rel3^T + b_rel3 ------------------------
__global__ void k_rel_out(const float* __restrict__ W_rel3,
                          const float* __restrict__ b_rel3,
                          float* __restrict__ out) {
    int r = blockIdx.x * 4 + (threadIdx.x >> 5);
    int lane = threadIdx.x & 31;
    if (r >= RR) return;
    int cnt = g_rel_off[r + 1] - g_rel_off[r];
    float inv = 1.f / (float)max(cnt, 1);
    int i0 = lane, i1 = lane + 32;
    float h0 = b_rel3[i0], h1 = b_rel3[i1];
#pragma unroll 4
    for (int jj = 0; jj < 128; jj++) {
        float m = g_relsum[r * 128 + jj] * inv;
        h0 = fmaf(W_rel3[i0 * 192 + jj], m, h0);
        h1 = fmaf(W_rel3[i1 * 192 + jj], m, h1);
    }
#pragma unroll 4
    for (int jj = 0; jj < 64; jj++) {
        float m = g_R2[r * DD + jj];
        h0 = fmaf(W_rel3[i0 * 192 + 128 + jj], m, h0);
        h1 = fmaf(W_rel3[i1 * 192 + 128 + jj], m, h1);
    }
    out[NN * DD + r * DD + i0] = h0;
    out[NN * DD + r * DD + i1] = h1;
}

// ---------------- launcher ---------------------------------------------------
extern "C" void kernel_launch(void* const* d_in, const int* in_sizes, int n_in,
                              void* d_out, int out_size) {
    const float* ent_embed = (const float*)d_in[0];
    const float* rel_embed = (const float*)d_in[1];
    const float* W_ent  = (const float*)d_in[2];
    const float* b_ent  = (const float*)d_in[3];
    const float* W_relL = (const float*)d_in[4];
    const float* b_relL = (const float*)d_in[5];
    const float* W_rel2 = (const float*)d_in[6];
    const float* b_rel2 = (const float*)d_in[7];
    const float* W_rel3 = (const float*)d_in[8];
    const float* b_rel3 = (const float*)d_in[9];
    const float* W_a    = (const float*)d_in[10];
    const float* b_a    = (const float*)d_in[11];
    const float* W_fc   = (const float*)d_in[12];
    const float* b_fc   = (const float*)d_in[13];
    const int* src_idx = (const int*)d_in[14];
    const int* dst_idx = (const int*)d_in[15];
    const int* rel_idx = (const int*)d_in[16];
    float* out = (float*)d_out;

    // one-time infra (handles only; no device memory)
    static cudaStream_t s2 = nullptr;
    static cudaEvent_t evF = nullptr, evJ = nullptr;
    if (s2 == nullptr) {
        cudaStreamCreateWithFlags(&s2, cudaStreamNonBlocking);
        cudaEventCreateWithFlags(&evF, cudaEventDisableTiming);
        cudaEventCreateWithFlags(&evJ, cudaEventDisableTiming);
    }

    void *pSrcCnt, *pRelCnt, *pRelSum;
    cudaGetSymbolAddress(&pSrcCnt, g_src_cnt);
    cudaGetSymbolAddress(&pRelCnt, g_rel_cnt);
    cudaGetSymbolAddress(&pRelSum, g_relsum);

    // fork: CSR chain on s2, projection chain on stream 0
    cudaEventRecord(evF, 0);
    cudaStreamWaitEvent(s2, evF, 0);

    // --- side stream: counts -> scans -> fill ---
    cudaMemsetAsync(pSrcCnt, 0, NN * sizeof(int), s2);
    cudaMemsetAsync(pRelCnt, 0, RR * RPAD * sizeof(int), s2);
    k_count<<<(EE / 4 + 255) / 256, 256, 0, s2>>>((const int4*)src_idx,
                                                  (const int4*)rel_idx);
    k_scan1<<<NB_N, 1024, 0, s2>>>();
    k_scan2<<<1, 128, 0, s2>>>();
    k_scan3<<<NB_N, 1024, 0, s2>>>();
    k_relscan<<<1, 512, 0, s2>>>();
    k_fill<<<(EE / 4 + 255) / 256, 256, 0, s2>>>((const int4*)src_idx,
                                                 (const int4*)rel_idx);
    cudaEventRecord(evJ, s2);

    // --- main stream: projections -> logits ---
    cudaMemsetAsync(pRelSum, 0, RR * 128 * sizeof(float), 0);
    k_precompute<<<1, 256>>>(W_ent, W_relL, W_fc, b_ent, b_relL, b_fc);
    k_rel_proj<<<(RR + 3) / 4, 128>>>(rel_embed, W_relL, b_relL, W_rel2, b_rel2, W_a, b_a);
    k_node_proj<<<(NN + 127) / 128, 128>>>(ent_embed, W_a);
    k_edge_logits<<<(EE / 4 + 255) / 256, 256>>>((const int4*)src_idx,
                                                 (const int4*)dst_idx,
                                                 (const int4*)rel_idx);

    // join, then aggregation
    cudaStreamWaitEvent(0, evJ, 0);
    k_node_agg<<<(NN + 7) / 8, 256>>>(dst_idx, rel_idx, out);
    k_rel_pool<<<RR * SPLIT, 128>>>(src_idx, dst_idx, (const float4*)out);
    k_rel_out<<<(RR + 3) / 4, 128>>>(W_rel3, b_rel3, out);
}

// round 4
// speedup vs baseline: 1.9956x; 1.0784x over previous
#include <cuda_runtime.h>
#include <cuda_bf16.h>
#include <math.h>

#define NN 100000
#define EE 1000000
#define RR 500
#define DD 64
#define NB_N 98            // ceil(100000/1024)
#define SPLIT 16
#define RPAD 32            // 128B stride for relation counters

typedef unsigned long long ull;

#define FMA2(d, a, b, c) \
    asm("fma.rn.f32x2 %0, %1, %2, %3;" : "=l"(d) : "l"(a), "l"(b), "l"(c))

__device__ __forceinline__ ull pack2(float lo, float hi) {
    return ((ull)__float_as_uint(hi) << 32) | (ull)__float_as_uint(lo);
}
__device__ __forceinline__ float lo2(ull u) { return __uint_as_float((unsigned)u); }
__device__ __forceinline__ float hi2(ull u) { return __uint_as_float((unsigned)(u >> 32)); }

// ---------------- scratch (device globals) ------------------------------------
__device__ __align__(16) float g_P1[NN * DD];
__device__ __align__(16) float g_P2[NN * DD];
__device__ float g_q1[NN];
__device__ float g_q2[NN];
__device__ __align__(16) float g_P3p[RR * DD];
__device__ float g_q3[RR];
__device__ float g_R2[RR * DD];
__device__ ull   g_M12[DD * DD];     // packed (M1, M2)
__device__ float g_M3[DD * DD];
__device__ float g_c0[DD];
__device__ int   g_src_cnt[NN];
__device__ int   g_rel_cnt[RR * RPAD];
__device__ int   g_src_off[NN + 1];
__device__ int   g_rel_off[RR + 1];
__device__ int   g_src_cur[NN];
__device__ int   g_rel_cur[RR * RPAD];
__device__ __align__(8) int2 g_src_pay[EE];   // (dst, rel) in src-CSR order
__device__ __align__(8) int2 g_rel_pay[EE];   // (src, dst) in rel-CSR order
__device__ int   g_blocksum[128];
__device__ float g_relsum[RR * 128];

// ---------------- helpers ----------------------------------------------------
__device__ __forceinline__ int blockExScan(int v, int* warpSums) {
    int lane = threadIdx.x & 31;
    int wid  = threadIdx.x >> 5;
    int nw   = blockDim.x >> 5;
    int inc = v;
#pragma unroll
    for (int o = 1; o < 32; o <<= 1) {
        int t = __shfl_up_sync(0xffffffffu, inc, o);
        if (lane >= o) inc += t;
    }
    if (lane == 31) warpSums[wid] = inc;
    __syncthreads();
    if (wid == 0) {
        int w = (lane < nw) ? warpSums[lane] : 0;
#pragma unroll
        for (int o = 1; o < 32; o <<= 1) {
            int t = __shfl_up_sync(0xffffffffu, w, o);
            if (lane >= o) w += t;
        }
        if (lane < nw) warpSums[lane] = w;
    }
    __syncthreads();
    int base = (wid > 0) ? warpSums[wid - 1] : 0;
    return base + inc - v;   // exclusive
}

// ---------------- 1. composed weight matrices --------------------------------
__global__ void k_precompute(const float* __restrict__ W_ent,
                             const float* __restrict__ W_relL,
                             const float* __restrict__ W_fc,
                             const float* __restrict__ b_ent,
                             const float* __restrict__ b_relL,
                             const float* __restrict__ b_fc) {
    int tid = threadIdx.x;
    for (int idx = tid; idx < DD * DD; idx += blockDim.x) {
        int i = idx >> 6, j = idx & 63;
        float a1 = 0.f, a2 = 0.f, a3 = 0.f;
#pragma unroll 8
        for (int k = 0; k < DD; k++) {
            float e = W_ent[k * DD + j];
            a1 = fmaf(W_fc[i * 192 + k], e, a1);
            a2 = fmaf(W_fc[i * 192 + 64 + k], e, a2);
            a3 = fmaf(W_fc[i * 192 + 128 + k], W_relL[k * DD + j], a3);
        }
        g_M12[idx] = pack2(a1, a2);
        g_M3[idx] = a3;
    }
    if (tid < DD) {
        float c = b_fc[tid];
#pragma unroll 8
        for (int k = 0; k < DD; k++) {
            c = fmaf(W_fc[tid * 192 + k], b_ent[k], c);
            c = fmaf(W_fc[tid * 192 + 64 + k], b_ent[k], c);
            c = fmaf(W_fc[tid * 192 + 128 + k], b_relL[k], c);
        }
        g_c0[tid] = c;
    }
}

// ---------------- 2. relation tables: P3p, q3, R2 ----------------------------
__global__ void k_rel_proj(const float* __restrict__ rel_embed,
                           const float* __restrict__ W_relL,
                           const float* __restrict__ b_relL,
                           const float* __restrict__ W_rel2,
                           const float* __restrict__ b_rel2,
                           const float* __restrict__ W_a,
                           const float* __restrict__ b_a) {
    int r = blockIdx.x * 4 + (threadIdx.x >> 5);
    int lane = threadIdx.x & 31;
    if (r >= RR) return;
    float x0 = rel_embed[r * DD + lane];
    float x1 = rel_embed[r * DD + 32 + lane];
    int i0 = lane, i1 = lane + 32;
    float rl0 = b_relL[i0], rl1 = b_relL[i1];
    float p0 = g_c0[i0], p1 = g_c0[i1];
#pragma unroll
    for (int k = 0; k < DD; k++) {
        float xk = (k < 32) ? __shfl_sync(0xffffffffu, x0, k)
                            : __shfl_sync(0xffffffffu, x1, k - 32);
        rl0 = fmaf(xk, W_relL[i0 * DD + k], rl0);
        rl1 = fmaf(xk, W_relL[i1 * DD + k], rl1);
        p0  = fmaf(xk, g_M3[i0 * DD + k], p0);
        p1  = fmaf(xk, g_M3[i1 * DD + k], p1);
    }
    g_P3p[r * DD + i0] = p0;
    g_P3p[r * DD + i1] = p1;
    float r20 = b_rel2[i0], r21 = b_rel2[i1];
#pragma unroll
    for (int k = 0; k < DD; k++) {
        float rk = (k < 32) ? __shfl_sync(0xffffffffu, rl0, k)
                            : __shfl_sync(0xffffffffu, rl1, k - 32);
        r20 = fmaf(rk, W_rel2[i0 * DD + k], r20);
        r21 = fmaf(rk, W_rel2[i1 * DD + k], r21);
    }
    g_R2[r * DD + i0] = r20;
    g_R2[r * DD + i1] = r21;
    float q = fmaf(p0, W_a[i0], p1 * W_a[i1]);
#pragma unroll
    for (int o = 16; o > 0; o >>= 1) q += __shfl_xor_sync(0xffffffffu, q, o);
    if (lane == 0) g_q3[r] = q + b_a[0];
}

// ---------------- 3. node tables via f32x2: P1, P2, q1, q2 -------------------
__global__ void __launch_bounds__(128) k_node_proj(const float* __restrict__ ent,
                                                   const float* __restrict__ W_a) {
    __shared__ ull sM[DD * DD];          // 32KB packed (M1,M2)
    __shared__ float sA[DD];
    for (int idx = threadIdx.x; idx < DD * DD; idx += 128) sM[idx] = g_M12[idx];
    if (threadIdx.x < DD) sA[threadIdx.x] = W_a[threadIdx.x];
    __syncthreads();

    int node = blockIdx.x * 128 + threadIdx.x;
    if (node >= NN) return;

    float xs[DD];
    const float4* xr = (const float4*)(ent + node * DD);
#pragma unroll
    for (int u = 0; u < 16; u++) {
        float4 v = xr[u];
        xs[4 * u + 0] = v.x; xs[4 * u + 1] = v.y;
        xs[4 * u + 2] = v.z; xs[4 * u + 3] = v.w;
    }
    float q1a = 0.f, q2a = 0.f;
#pragma unroll 1
    for (int g = 0; g < 4; g++) {
        ull acc[16];
#pragma unroll
        for (int ii = 0; ii < 16; ii++) acc[ii] = 0ULL;
#pragma unroll 8
        for (int k = 0; k < DD; k++) {
            ull xx = pack2(xs[k], xs[k]);
#pragma unroll
            for (int ii = 0; ii < 16; ii++) {
                FMA2(acc[ii], xx, sM[(g * 16 + ii) * DD + k], acc[ii]);
            }
        }
#pragma unroll
        for (int ii = 0; ii < 16; ii += 4) {
            int i = g * 16 + ii;
            float p10 = lo2(acc[ii]),     p20 = hi2(acc[ii]);
            float p11 = lo2(acc[ii + 1]), p21 = hi2(acc[ii + 1]);
            float p12 = lo2(acc[ii + 2]), p22 = hi2(acc[ii + 2]);
            float p13 = lo2(acc[ii + 3]), p23 = hi2(acc[ii + 3]);
            *(float4*)&g_P1[node * DD + i] = make_float4(p10, p11, p12, p13);
            *(float4*)&g_P2[node * DD + i] = make_float4(p20, p21, p22, p23);
            q1a = fmaf(p10, sA[i], q1a);     q2a = fmaf(p20, sA[i], q2a);
            q1a = fmaf(p11, sA[i + 1], q1a); q2a = fmaf(p21, sA[i + 1], q2a);
            q1a = fmaf(p12, sA[i + 2], q1a); q2a = fmaf(p22, sA[i + 2], q2a);
            q1a = fmaf(p13, sA[i + 3], q1a); q2a = fmaf(p23, sA[i + 3], q2a);
        }
    }
    g_q1[node] = q1a;
    g_q2[node] = q2a;
}

// ---------------- 4. counts (side stream) ------------------------------------
__global__ void __launch_bounds__(256) k_count(const int4* __restrict__ src4,
                                               const int4* __restrict__ rel4) {
    int t = blockIdx.x * blockDim.x + threadIdx.x;
    if (t >= EE / 4) return;
    int4 s = src4[t], r = rel4[t];
    atomicAdd(&g_src_cnt[s.x], 1);
    atomicAdd(&g_src_cnt[s.y], 1);
    atomicAdd(&g_src_cnt[s.z], 1);
    atomicAdd(&g_src_cnt[s.w], 1);
    atomicAdd(&g_rel_cnt[r.x * RPAD], 1);
    atomicAdd(&g_rel_cnt[r.y * RPAD], 1);
    atomicAdd(&g_rel_cnt[r.z * RPAD], 1);
    atomicAdd(&g_rel_cnt[r.w * RPAD], 1);
}

// ---------------- 5. scans / CSR build ---------------------------------------
__global__ void k_scan1() {
    __shared__ int ws[32];
    int i = blockIdx.x * 1024 + threadIdx.x;
    int v = (i < NN) ? g_src_cnt[i] : 0;
    int lane = threadIdx.x & 31, wid = threadIdx.x >> 5;
#pragma unroll
    for (int o = 16; o > 0; o >>= 1) v += __shfl_down_sync(0xffffffffu, v, o);
    if (lane == 0) ws[wid] = v;
    __syncthreads();
    if (wid == 0) {
        int s = ws[lane];
#pragma unroll
        for (int o = 16; o > 0; o >>= 1) s += __shfl_down_sync(0xffffffffu, s, o);
        if (lane == 0) g_blocksum[blockIdx.x] = s;
    }
}
__global__ void k_scan2() {
    __shared__ int ws[32];
    int v = (threadIdx.x < NB_N) ? g_blocksum[threadIdx.x] : 0;
    int ex = blockExScan(v, ws);
    if (threadIdx.x < NB_N) g_blocksum[threadIdx.x] = ex;
    if (threadIdx.x == 0) g_src_off[NN] = EE;
}
__global__ void k_scan3() {
    __shared__ int ws[32];
    int i = blockIdx.x * 1024 + threadIdx.x;
    int v = (i < NN) ? g_src_cnt[i] : 0;
    int ex = blockExScan(v, ws) + g_blocksum[blockIdx.x];
    if (i < NN) { g_src_off[i] = ex; g_src_cur[i] = ex; }
}
__global__ void k_relscan() {
    __shared__ int ws[32];
    int i = threadIdx.x;
    int v = (i < RR) ? g_rel_cnt[i * RPAD] : 0;
    int ex = blockExScan(v, ws);
    if (i < RR) { g_rel_off[i] = ex; g_rel_cur[i * RPAD] = ex; }
    if (i == 0) g_rel_off[RR] = EE;
}
__global__ void __launch_bounds__(256) k_fill(const int4* __restrict__ src4,
                                              const int4* __restrict__ dst4,
                                              const int4* __restrict__ rel4) {
    int t = blockIdx.x * blockDim.x + threadIdx.x;
    if (t >= EE / 4) return;
    int4 s = src4[t], d = dst4[t], r = rel4[t];
    g_src_pay[atomicAdd(&g_src_cur[s.x], 1)] = make_int2(d.x, r.x);
    g_src_pay[atomicAdd(&g_src_cur[s.y], 1)] = make_int2(d.y, r.y);
    g_src_pay[atomicAdd(&g_src_cur[s.z], 1)] = make_int2(d.z, r.z);
    g_src_pay[atomicAdd(&g_src_cur[s.w], 1)] = make_int2(d.w, r.w);
    g_rel_pay[atomicAdd(&g_rel_cur[r.x * RPAD], 1)] = make_int2(s.x, d.x);
    g_rel_pay[atomicAdd(&g_rel_cur[r.y * RPAD], 1)] = make_int2(s.y, d.y);
    g_rel_pay[atomicAdd(&g_rel_cur[r.z * RPAD], 1)] = make_int2(s.z, d.z);
    g_rel_pay[atomicAdd(&g_rel_cur[r.w * RPAD], 1)] = make_int2(s.w, d.w);
}

// ---------------- 6. node aggregation: h_ent ---------------------------------
// warp per node; payload contiguous; b computed inline (src==n uniform)
__global__ void __launch_bounds__(256) k_node_agg(float* __restrict__ out) {
    const float4* P1 = (const float4*)g_P1;
    const float4* P2 = (const float4*)g_P2;
    const float4* P3 = (const float4*)g_P3p;
    int wid = threadIdx.x >> 5;
    int lane = threadIdx.x & 31;
    int n = blockIdx.x * 8 + wid;
    if (n >= NN) return;
    int j0 = g_src_off[n];
    int j1 = g_src_off[n + 1];
    int half = lane >> 4;
    int q = lane & 15;
    float q1n = g_q1[n];
    float4 acc = make_float4(0.f, 0.f, 0.f, 0.f);
    float bsum = 0.f;
    int j = j0 + half;
    for (; j + 2 < j1; j += 4) {
        int2 pA = g_src_pay[j];
        int2 pB = g_src_pay[j + 2];
        float lA = q1n + g_q2[pA.x] + g_q3[pA.y];
        float lB = q1n + g_q2[pB.x] + g_q3[pB.y];
        lA = (lA >= 0.f) ? lA : 0.01f * lA;
        lB = (lB >= 0.f) ? lB : 0.01f * lB;
        float bA = expf(lA), bB = expf(lB);
        float4 vA = P2[pA.x * 16 + q];
        float4 tA = P3[pA.y * 16 + q];
        float4 vB = P2[pB.x * 16 + q];
        float4 tB = P3[pB.y * 16 + q];
        acc.x = fmaf(bA, vA.x + tA.x, acc.x); acc.x = fmaf(bB, vB.x + tB.x, acc.x);
        acc.y = fmaf(bA, vA.y + tA.y, acc.y); acc.y = fmaf(bB, vB.y + tB.y, acc.y);
        acc.z = fmaf(bA, vA.z + tA.z, acc.z); acc.z = fmaf(bB, vB.z + tB.z, acc.z);
        acc.w = fmaf(bA, vA.w + tA.w, acc.w); acc.w = fmaf(bB, vB.w + tB.w, acc.w);
        bsum += bA + bB;
    }
    if (j < j1) {
        int2 p = g_src_pay[j];
        float lg = q1n + g_q2[p.x] + g_q3[p.y];
        lg = (lg >= 0.f) ? lg : 0.01f * lg;
        float b = expf(lg);
        float4 v = P2[p.x * 16 + q];
        float4 tq = P3[p.y * 16 + q];
        acc.x = fmaf(b, v.x + tq.x, acc.x);
        acc.y = fmaf(b, v.y + tq.y, acc.y);
        acc.z = fmaf(b, v.z + tq.z, acc.z);
        acc.w = fmaf(b, v.w + tq.w, acc.w);
        bsum += b;
    }
    acc.x += __shfl_down_sync(0xffffffffu, acc.x, 16);
    acc.y += __shfl_down_sync(0xffffffffu, acc.y, 16);
    acc.z += __shfl_down_sync(0xffffffffu, acc.z, 16);
    acc.w += __shfl_down_sync(0xffffffffu, acc.w, 16);
    bsum  += __shfl_down_sync(0xffffffffu, bsum, 16);
    if (half == 0) {
        float4 h;
        if (j1 > j0) {
            float inv = 1.f / bsum;
            float4 p1 = P1[n * 16 + q];
            h.x = p1.x + acc.x * inv;
            h.y = p1.y + acc.y * inv;
            h.z = p1.z + acc.z * inv;
            h.w = p1.w + acc.w * inv;
        } else {
            h = make_float4(0.f, 0.f, 0.f, 0.f);
        }
        ((float4*)out)[n * 16 + q] = h;
    }
}

// ---------------- 7. relation pooling sums (float4, payload) -----------------
__global__ void __launch_bounds__(128) k_rel_pool(const float4* __restrict__ h4) {
    __shared__ float4 sred[4][32];
    int r = blockIdx.x >> 4;
    int part = blockIdx.x & (SPLIT - 1);
    int b0 = g_rel_off[r], b1 = g_rel_off[r + 1];
    int len = b1 - b0;
    int per = (len + SPLIT - 1) >> 4;
    int j0 = b0 + part * per;
    int j1 = min(j0 + per, b1);
    int t = threadIdx.x;
    int eslot = t >> 5;            // 0..3
    int lane = t & 31;
    int isDst = lane >> 4;
    int q = lane & 15;
    float4 acc = make_float4(0.f, 0.f, 0.f, 0.f);
    int j = j0 + eslot;
    for (; j + 4 < j1; j += 8) {
        int2 pA = g_rel_pay[j];
        int2 pB = g_rel_pay[j + 4];
        int nA = isDst ? pA.y : pA.x;
        int nB = isDst ? pB.y : pB.x;
        float4 vA = h4[nA * 16 + q];
        float4 vB = h4[nB * 16 + q];
        acc.x += vA.x + vB.x;
        acc.y += vA.y + vB.y;
        acc.z += vA.z + vB.z;
        acc.w += vA.w + vB.w;
    }
    if (j < j1) {
        int2 p = g_rel_pay[j];
        int n = isDst ? p.y : p.x;
        float4 v = h4[n * 16 + q];
        acc.x += v.x; acc.y += v.y; acc.z += v.z; acc.w += v.w;
    }
    sred[eslot][lane] = acc;
    __syncthreads();
    if (eslot == 0) {
        float4 a = sred[0][lane], b = sred[1][lane], c = sred[2][lane], d = sred[3][lane];
        float sx = (a.x + b.x) + (c.x + d.x);
        float sy = (a.y + b.y) + (c.y + d.y);
        float sz = (a.z + b.z) + (c.z + d.z);
        float sw = (a.w + b.w) + (c.w + d.w);
        int base = r * 128 + isDst * 64 + q * 4;
        atomicAdd(&g_relsum[base + 0], sx);
        atomicAdd(&g_relsum[base + 1], sy);
        atomicAdd(&g_relsum[base + 2], sz);
        atomicAdd(&g_relsum[base + 3], sw);
    }
}

// ---------------- 8. h_rel = mean @ W_rel3^T + b_rel3 ------------------------
__global__ void k_rel_out(const float* __restrict__ W_rel3,
                          const float* __restrict__ b_rel3,
                          float* __restrict__ out) {
    int r = blockIdx.x * 4 + (threadIdx.x >> 5);
    int lane = threadIdx.x & 31;
    if (r >= RR) return;
    int cnt = g_rel_off[r + 1] - g_rel_off[r];
    float inv = 1.f / (float)max(cnt, 1);
    int i0 = lane, i1 = lane + 32;
    float h0 = b_rel3[i0], h1 = b_rel3[i1];
#pragma unroll 4
    for (int jj = 0; jj < 128; jj++) {
        float m = g_relsum[r * 128 + jj] * inv;
        h0 = fmaf(W_rel3[i0 * 192 + jj], m, h0);
        h1 = fmaf(W_rel3[i1 * 192 + jj], m, h1);
    }
#pragma unroll 4
    for (int jj = 0; jj < 64; jj++) {
        float m = g_R2[r * DD + jj];
        h0 = fmaf(W_rel3[i0 * 192 + 128 + jj], m, h0);
        h1 = fmaf(W_rel3[i1 * 192 + 128 + jj], m, h1);
    }
    out[NN * DD + r * DD + i0] = h0;
    out[NN * DD + r * DD + i1] = h1;
}

// ---------------- launcher ---------------------------------------------------
extern "C" void kernel_launch(void* const* d_in, const int* in_sizes, int n_in,
                              void* d_out, int out_size) {
    const float* ent_embed = (const float*)d_in[0];
    const float* rel_embed = (const float*)d_in[1];
    const float* W_ent  = (const float*)d_in[2];
    const float* b_ent  = (const float*)d_in[3];
    const float* W_relL = (const float*)d_in[4];
    const float* b_relL = (const float*)d_in[5];
    const float* W_rel2 = (const float*)d_in[6];
    const float* b_rel2 = (const float*)d_in[7];
    const float* W_rel3 = (const float*)d_in[8];
    const float* b_rel3 = (const float*)d_in[9];
    const float* W_a    = (const float*)d_in[10];
    const float* b_a    = (const float*)d_in[11];
    const float* W_fc   = (const float*)d_in[12];
    const float* b_fc   = (const float*)d_in[13];
    const int* src_idx = (const int*)d_in[14];
    const int* dst_idx = (const int*)d_in[15];
    const int* rel_idx = (const int*)d_in[16];
    float* out = (float*)d_out;

    static cudaStream_t s2 = nullptr;
    static cudaEvent_t evF = nullptr, evJ = nullptr;
    if (s2 == nullptr) {
        cudaStreamCreateWithFlags(&s2, cudaStreamNonBlocking);
        cudaEventCreateWithFlags(&evF, cudaEventDisableTiming);
        cudaEventCreateWithFlags(&evJ, cudaEventDisableTiming);
    }

    void *pSrcCnt, *pRelCnt, *pRelSum;
    cudaGetSymbolAddress(&pSrcCnt, g_src_cnt);
    cudaGetSymbolAddress(&pRelCnt, g_rel_cnt);
    cudaGetSymbolAddress(&pRelSum, g_relsum);

    // fork: CSR chain on s2, projection chain on stream 0
    cudaEventRecord(evF, 0);
    cudaStreamWaitEvent(s2, evF, 0);

    // --- side stream: counts -> scans -> fill (payload CSR) ---
    cudaMemsetAsync(pSrcCnt, 0, NN * sizeof(int), s2);
    cudaMemsetAsync(pRelCnt, 0, RR * RPAD * sizeof(int), s2);
    k_count<<<(EE / 4 + 255) / 256, 256, 0, s2>>>((const int4*)src_idx,
                                                  (const int4*)rel_idx);
    k_scan1<<<NB_N, 1024, 0, s2>>>();
    k_scan2<<<1, 128, 0, s2>>>();
    k_scan3<<<NB_N, 1024, 0, s2>>>();
    k_relscan<<<1, 512, 0, s2>>>();
    k_fill<<<(EE / 4 + 255) / 256, 256, 0, s2>>>((const int4*)src_idx,
                                                 (const int4*)dst_idx,
                                                 (const int4*)rel_idx);
    cudaEventRecord(evJ, s2);

    // --- main stream: projections ---
    cudaMemsetAsync(pRelSum, 0, RR * 128 * sizeof(float), 0);
    k_precompute<<<1, 256>>>(W_ent, W_relL, W_fc, b_ent, b_relL, b_fc);
    k_rel_proj<<<(RR + 3) / 4, 128>>>(rel_embed, W_relL, b_relL, W_rel2, b_rel2, W_a, b_a);
    k_node_proj<<<(NN + 127) / 128, 128>>>(ent_embed, W_a);

    // join, then aggregation
    cudaStreamWaitEvent(0, evJ, 0);
    k_node_agg<<<(NN + 7) / 8, 256>>>(out);
    k_rel_pool<<<RR * SPLIT, 128>>>((const float4*)out);
    k_rel_out<<<(RR + 3) / 4, 128>>>(W_rel3, b_rel3, out);
}